// round 16
// baseline (speedup 1.0000x reference)
#include <cuda_runtime.h>
#include <cuda_fp16.h>
#include <cstdint>

#define BSZ 256   // batch
#define SS  512   // seq
#define II  128   // in features
#define OO  128   // out features
#define LLG 11    // lags (MAX_LAG+1)
#define HH  16    // modulator hidden
#define BT  8     // b-tile for hist transpose
#define ICH 12    // i-chunks: 8x11 + 4x10
#define MAXL 11
#define OQ  4     // o's per main block

// ---- device scratch (recomputed every launch; graph-safe) ----------------
__device__ uint4  g_hist4[(II * BSZ * 24) / 16];  // [i][b][12] halves, 768KB
__device__ float  g_xmf[II * BSZ];                // [i][b] mean, 128KB
__device__ float4 g_xmp[4][BSZ][32];              // xm partials (4 quarters), 512KB

// 64B per (o,i): lag weights (half2), spline coeffs, modulator cubic
struct PP2 {
    __half2 wl2[6];          // softmax lag weights, [11]=0 pad (24B)
    float   C[5];            // edge-masked coeffs (knots 0..4)  (20B)
    float   A0, K1, K2, K3;  // alpha = sigmoid(A0+K1*xm+K2*xm^2+K3*xm^3)
};
union UP2 { uint4 v[4]; PP2 p; };
__device__ uint4 g_pp2[OO * II * 4];              // 1MB

__device__ __forceinline__ float tanh_fast(float x) {
    float y;
    asm("tanh.approx.f32 %0, %1;" : "=f"(y) : "f"(x));
    return y;
}
__device__ __forceinline__ float sigmoid_t(float x) {   // 1 MUFU
    return fmaf(tanh_fast(0.5f * x), 0.5f, 0.5f);
}
__device__ __forceinline__ void cp16(uint32_t dst, const void* src) {
    asm volatile("cp.async.cg.shared.global [%0], [%1], 16;" :: "r"(dst), "l"(src));
}

// ---------------------------------------------------------------------------
// Kernel 1: xm partials (blocks 0..1023) + param pack (blocks 1024..1087).
// The pack work (no smem, ~1us) hides inside the BW-bound xm time.
// ---------------------------------------------------------------------------
__global__ __launch_bounds__(256) void xm_kernel(
    const float* __restrict__ x,
    const float* __restrict__ coeffs,
    const float* __restrict__ lag_logits,
    const float* __restrict__ mw1,
    const float* __restrict__ mb1,
    const float* __restrict__ mw2,
    const float* __restrict__ mb2,
    const float* __restrict__ edge,
    float* __restrict__ out)
{
    int tid = threadIdx.x;
    int bx  = blockIdx.x;

    if (bx < 1024) {
        int b  = bx & 255;
        int q  = bx >> 8;
        int i4 = tid & 31;
        int rg = tid >> 5;          // 0..7, 16 rows each
        if (q == 0 && tid < OO) out[(size_t)b * OO + tid] = 0.0f;

        const float4* p = reinterpret_cast<const float4*>(x + (size_t)b * SS * II)
                          + ((size_t)q * 128 + rg * 16) * 32 + i4;
        float4 s = make_float4(0.f, 0.f, 0.f, 0.f);
#pragma unroll 16
        for (int r = 0; r < 16; r++) {
            float4 v = p[(size_t)r * 32];
            s.x += v.x; s.y += v.y; s.z += v.z; s.w += v.w;
        }
        __shared__ float4 red[8][32];
        red[rg][i4] = s;
        __syncthreads();
        if (tid < 32) {
            float4 a = red[0][tid];
#pragma unroll
            for (int g = 1; g < 8; g++) {
                float4 v = red[g][tid];
                a.x += v.x; a.y += v.y; a.z += v.z; a.w += v.w;
            }
            g_xmp[q][b][tid] = a;
        }
        return;
    }

    // ---- param pack ----
    int oi = (bx - 1024) * 256 + tid;
    UP2 u;

    float wl[LLG];
    float m = -1e30f;
#pragma unroll
    for (int l = 0; l < LLG; l++) { wl[l] = lag_logits[oi * LLG + l]; m = fmaxf(m, wl[l]); }
    float sum = 0.0f;
#pragma unroll
    for (int l = 0; l < LLG; l++) { wl[l] = __expf(wl[l] - m); sum += wl[l]; }
    float inv = __fdividef(1.0f, sum);
#pragma unroll
    for (int l = 0; l < LLG; l++) wl[l] *= inv;
#pragma unroll
    for (int k = 0; k < 5; k++)
        u.p.wl2[k] = __floats2half2_rn(wl[2 * k], wl[2 * k + 1]);
    u.p.wl2[5] = __floats2half2_rn(wl[10], 0.0f);

    float mask = (edge[oi] > 0.0f) ? 1.0f : 0.0f;
#pragma unroll
    for (int j = 0; j < 5; j++) u.p.C[j] = coeffs[oi * 8 + j] * mask;

    // modulator MLP -> cubic in xm (Taylor about b1; |xm*w1| < 0.1)
    float A0 = mb2[oi], K1 = 0.f, K2 = 0.f, K3 = 0.f;
#pragma unroll
    for (int h = 0; h < HH; h++) {
        float w1 = mw1[oi * HH + h];
        float b1 = mb1[oi * HH + h];
        float w2 = mw2[oi * HH + h];
        float T = tanhf(b1);
        float S = 1.0f - T * T;
        float w1w2 = w1 * w2;
        A0 += T * w2;
        K1 += S * w1w2;
        K2 -= S * T * w1 * w1w2;
        K3 += S * (3.0f * T * T - 1.0f) * (1.0f / 3.0f) * w1 * w1 * w1w2;
    }
    u.p.A0 = A0; u.p.K1 = K1; u.p.K2 = K2; u.p.K3 = K3;

    uint4* dst = g_pp2 + (size_t)oi * 4;
#pragma unroll
    for (int j = 0; j < 4; j++) dst[j] = u.v[j];
}

// ---------------------------------------------------------------------------
// Kernel 2: prep — xm finish (coalesced) + hist transpose.  32 blocks.
// ---------------------------------------------------------------------------
__global__ __launch_bounds__(256) void prep_kernel(const float* __restrict__ x)
{
    int tid = threadIdx.x;

    // ---- xm finish ----
    {
        int w    = blockIdx.x * 8 + (tid >> 5);   // 0..255
        int lane = tid & 31;
        int i4   = w & 31;
        int b    = (w >> 5) * 32 + lane;
        float4 a = g_xmp[0][b][i4];
#pragma unroll
        for (int q = 1; q < 4; q++) {
            float4 v = g_xmp[q][b][i4];
            a.x += v.x; a.y += v.y; a.z += v.z; a.w += v.w;
        }
        const float k = 1.0f / SS;
        g_xmf[(i4 * 4 + 0) * BSZ + b] = a.x * k;
        g_xmf[(i4 * 4 + 1) * BSZ + b] = a.y * k;
        g_xmf[(i4 * 4 + 2) * BSZ + b] = a.z * k;
        g_xmf[(i4 * 4 + 3) * BSZ + b] = a.w * k;
    }

    // ---- hist transpose ----
    __shared__ __align__(16) __half t[128][BT][12];   // 24576B
    int b0 = blockIdx.x * BT;
#pragma unroll
    for (int bb = 0; bb < BT; bb++) {
        int b = b0 + bb;
        for (int idx = tid; idx < 12 * 128; idx += 256) {
            int r = idx >> 7, i = idx & 127;
            __half v = __float2half(0.0f);
            int l = 11;
            if (r < 11) {          // row r holds s = SS-11+r  ->  lag l = 10-r
                l = 10 - r;
                v = __float2half(x[((size_t)b * SS + (SS - 11 + r)) * II + i]);
            }
            t[i][bb][l] = v;
        }
    }
    __syncthreads();

    const uint4* s4 = reinterpret_cast<const uint4*>(&t[0][0][0]);
    int boff = (b0 * 3) >> 1;
    for (int c = tid; c < 1536; c += 256) {
        int i = c / 12, j = c - i * 12;
        g_hist4[(size_t)i * 384 + boff + j] = s4[c];
    }
}

// ---------------------------------------------------------------------------
// One (b,o,i) from smem params + hist regs + xm.
// ---------------------------------------------------------------------------
__device__ __forceinline__ float eval(const uint4* __restrict__ sp, int ii,
                                      uint2 ha, uint2 hb, uint2 hc, float xm) {
    UP2 u;
#pragma unroll
    for (int j = 0; j < 4; j++) u.v[j] = sp[ii * 4 + j];

    __half2 d = __hmul2(*reinterpret_cast<__half2*>(&ha.x), u.p.wl2[0]);
    d = __hfma2(*reinterpret_cast<__half2*>(&ha.y), u.p.wl2[1], d);
    d = __hfma2(*reinterpret_cast<__half2*>(&hb.x), u.p.wl2[2], d);
    d = __hfma2(*reinterpret_cast<__half2*>(&hb.y), u.p.wl2[3], d);
    d = __hfma2(*reinterpret_cast<__half2*>(&hc.x), u.p.wl2[4], d);
    d = __hfma2(*reinterpret_cast<__half2*>(&hc.y), u.p.wl2[5], d);
    float2 df = __half22float2(d);
    float xl = df.x + df.y;

    float s   = sigmoid_t(xl);
    float idx = s * 4.0f;
    int   k   = (int)idx;
    k = (k > 3) ? 3 : k;
    float w1f = idx - (float)k;
    float c0 = (k == 0) ? u.p.C[0] : (k == 1) ? u.p.C[1] : (k == 2) ? u.p.C[2] : u.p.C[3];
    float c1 = (k == 0) ? u.p.C[1] : (k == 1) ? u.p.C[2] : (k == 2) ? u.p.C[3] : u.p.C[4];
    float y  = fmaf(c1 - c0, w1f, c0);

    float acc = fmaf(fmaf(fmaf(u.p.K3, xm, u.p.K2), xm, u.p.K1), xm, u.p.A0);
    float alpha = sigmoid_t(acc);
    return y * alpha;
}

// ---------------------------------------------------------------------------
// Kernel 3: main.  block = o-quad x i-chunk, 256 threads = 256 b.
// One hist/xm load feeds 4 independent eval chains (ILP x4); params staged
// to smem; hist/xm register-prefetched 1 ahead.  grid = (32, 12), occ 3.
// ---------------------------------------------------------------------------
__global__ __launch_bounds__(256, 3) void main_kernel(float* __restrict__ out)
{
    __shared__ __align__(16) uint4 spar[OQ][MAXL * 4];   // 2816B

    int b  = threadIdx.x;
    int o0 = blockIdx.x * OQ;
    int ch = blockIdx.y;
    int i0  = (ch < 8) ? ch * 11 : 88 + (ch - 8) * 10;
    int len = (ch < 8) ? 11 : 10;

    // stage all 4 o's params for this i-chunk
    {
        for (int oo = 0; oo < OQ; oo++) {
            const uint4* pg = g_pp2 + (size_t)((o0 + oo) * II + i0) * 4;
            uint32_t sb = (uint32_t)__cvta_generic_to_shared(&spar[oo][0]);
            for (int c = threadIdx.x; c < len * 4; c += 256)
                cp16(sb + c * 16, pg + c);
        }
        asm volatile("cp.async.commit_group;");
        asm volatile("cp.async.wait_group 0;");
    }
    __syncthreads();

    const uint2* hp = reinterpret_cast<const uint2*>(g_hist4) + ((size_t)i0 * BSZ + b) * 3;
    const float* xp = g_xmf + (size_t)i0 * BSZ + b;

    uint2 ha = hp[0], hb = hp[1], hc = hp[2];
    float xm = *xp;
    float acc0 = 0.0f, acc1 = 0.0f, acc2 = 0.0f, acc3 = 0.0f;

    for (int ii = 0; ii < len; ii++) {
        uint2 na = ha, nb = hb, nc = hc;
        float nx = xm;
        if (ii + 1 < len) {
            const uint2* q = hp + (size_t)(ii + 1) * BSZ * 3;
            na = q[0]; nb = q[1]; nc = q[2];
            nx = xp[(size_t)(ii + 1) * BSZ];
        }

        acc0 += eval(spar[0], ii, ha, hb, hc, xm);
        acc1 += eval(spar[1], ii, ha, hb, hc, xm);
        acc2 += eval(spar[2], ii, ha, hb, hc, xm);
        acc3 += eval(spar[3], ii, ha, hb, hc, xm);

        ha = na; hb = nb; hc = nc; xm = nx;
    }

    float* op = out + (size_t)b * OO + o0;
    atomicAdd(op,     acc0);
    atomicAdd(op + 1, acc1);
    atomicAdd(op + 2, acc2);
    atomicAdd(op + 3, acc3);
}

extern "C" void kernel_launch(void* const* d_in, const int* in_sizes, int n_in,
                              void* d_out, int out_size) {
    const float* x      = (const float*)d_in[0];
    const float* coeffs = (const float*)d_in[1];
    const float* lag    = (const float*)d_in[2];
    const float* mw1    = (const float*)d_in[3];
    const float* mb1    = (const float*)d_in[4];
    const float* mw2    = (const float*)d_in[5];
    const float* mb2    = (const float*)d_in[6];
    const float* edge   = (const float*)d_in[7];
    float* out = (float*)d_out;

    xm_kernel<<<1088, 256>>>(x, coeffs, lag, mw1, mb1, mw2, mb2, edge, out);
    prep_kernel<<<32, 256>>>(x);
    dim3 grid(OO / OQ, ICH);
    main_kernel<<<grid, 256>>>(out);
}

// round 17
// speedup vs baseline: 1.7833x; 1.7833x over previous
#include <cuda_runtime.h>
#include <cuda_fp16.h>
#include <cstdint>

#define BSZ 256   // batch
#define SS  512   // seq
#define II  128   // in features
#define OO  128   // out features
#define LLG 11    // lags (MAX_LAG+1)
#define HH  16    // modulator hidden
#define BT  8     // b-tile for hist transpose
#define ICH 12    // i-chunks: 8x11 + 4x10
#define MAXL 11
#define OQ  4     // o's per main block

// ---- device scratch (recomputed every launch; graph-safe) ----------------
__device__ uint4  g_hist4[(II * BSZ * 24) / 16];  // [i][b][12] halves, 768KB
__device__ float  g_xmf[II * BSZ];                // [i][b] mean, 128KB
__device__ float4 g_xmp[4][BSZ][32];              // xm partials (4 quarters), 512KB

// 64B per (o,i): lag weights (half2), spline coeffs, modulator cubic
struct PP2 {
    __half2 wl2[6];          // softmax lag weights, [11]=0 pad (24B)
    float   C[5];            // edge-masked coeffs (knots 0..4)  (20B)
    float   A0, K1, K2, K3;  // alpha = sigmoid(A0+K1*xm+K2*xm^2+K3*xm^3)
};
union UP2 { uint4 v[4]; PP2 p; };
__device__ uint4 g_pp2[OO * II * 4];              // 1MB

__device__ __forceinline__ float tanh_fast(float x) {
    float y;
    asm("tanh.approx.f32 %0, %1;" : "=f"(y) : "f"(x));
    return y;
}
__device__ __forceinline__ float sigmoid_t(float x) {   // 1 MUFU
    return fmaf(tanh_fast(0.5f * x), 0.5f, 0.5f);
}
__device__ __forceinline__ void cp16(uint32_t dst, const void* src) {
    asm volatile("cp.async.cg.shared.global [%0], [%1], 16;" :: "r"(dst), "l"(src));
}

// ---------------------------------------------------------------------------
// Kernel 1: xm partials ONLY (the BW-bound streamer rides alone — fusing any
// other work into this launch measurably destroys its DRAM utilization).
// grid (b, quarter) = (256,4) x 256 thr; 16 LDG.128 per thread.
// ---------------------------------------------------------------------------
__global__ __launch_bounds__(256) void xm_kernel(const float* __restrict__ x,
                                                 float* __restrict__ out) {
    int b  = blockIdx.x;
    int q  = blockIdx.y;
    int t  = threadIdx.x;
    int i4 = t & 31;
    int rg = t >> 5;          // 0..7, 16 rows each
    if (q == 0 && t < OO) out[(size_t)b * OO + t] = 0.0f;

    const float4* p = reinterpret_cast<const float4*>(x + (size_t)b * SS * II)
                      + ((size_t)q * 128 + rg * 16) * 32 + i4;
    float4 s = make_float4(0.f, 0.f, 0.f, 0.f);
#pragma unroll 16
    for (int r = 0; r < 16; r++) {
        float4 v = p[(size_t)r * 32];
        s.x += v.x; s.y += v.y; s.z += v.z; s.w += v.w;
    }
    __shared__ float4 red[8][32];
    red[rg][i4] = s;
    __syncthreads();
    if (t < 32) {
        float4 a = red[0][t];
#pragma unroll
        for (int g = 1; g < 8; g++) {
            float4 v = red[g][t];
            a.x += v.x; a.y += v.y; a.z += v.z; a.w += v.w;
        }
        g_xmp[q][b][t] = a;
    }
}

// ---------------------------------------------------------------------------
// Kernel 2: fused prep.  blocks 0..31: xm finish + hist transpose.
//           blocks 32..95: per-(o,i) param pack.   (R15-proven)
// ---------------------------------------------------------------------------
__global__ __launch_bounds__(256) void prep_kernel(
    const float* __restrict__ x,
    const float* __restrict__ coeffs,
    const float* __restrict__ lag_logits,
    const float* __restrict__ mw1,
    const float* __restrict__ mb1,
    const float* __restrict__ mw2,
    const float* __restrict__ mb2,
    const float* __restrict__ edge)
{
    int tid = threadIdx.x;

    if (blockIdx.x >= 32) {
        // ---- param pack ----
        int oi = (blockIdx.x - 32) * 256 + tid;
        UP2 u;

        float wl[LLG];
        float m = -1e30f;
#pragma unroll
        for (int l = 0; l < LLG; l++) { wl[l] = lag_logits[oi * LLG + l]; m = fmaxf(m, wl[l]); }
        float sum = 0.0f;
#pragma unroll
        for (int l = 0; l < LLG; l++) { wl[l] = __expf(wl[l] - m); sum += wl[l]; }
        float inv = __fdividef(1.0f, sum);
#pragma unroll
        for (int l = 0; l < LLG; l++) wl[l] *= inv;
#pragma unroll
        for (int k = 0; k < 5; k++)
            u.p.wl2[k] = __floats2half2_rn(wl[2 * k], wl[2 * k + 1]);
        u.p.wl2[5] = __floats2half2_rn(wl[10], 0.0f);

        float mask = (edge[oi] > 0.0f) ? 1.0f : 0.0f;
#pragma unroll
        for (int j = 0; j < 5; j++) u.p.C[j] = coeffs[oi * 8 + j] * mask;

        // modulator MLP -> cubic in xm (Taylor about b1; |xm*w1| < 0.1)
        float A0 = mb2[oi], K1 = 0.f, K2 = 0.f, K3 = 0.f;
#pragma unroll
        for (int h = 0; h < HH; h++) {
            float w1 = mw1[oi * HH + h];
            float b1 = mb1[oi * HH + h];
            float w2 = mw2[oi * HH + h];
            float T = tanhf(b1);
            float S = 1.0f - T * T;
            float w1w2 = w1 * w2;
            A0 += T * w2;
            K1 += S * w1w2;
            K2 -= S * T * w1 * w1w2;
            K3 += S * (3.0f * T * T - 1.0f) * (1.0f / 3.0f) * w1 * w1 * w1w2;
        }
        u.p.A0 = A0; u.p.K1 = K1; u.p.K2 = K2; u.p.K3 = K3;

        uint4* dst = g_pp2 + (size_t)oi * 4;
#pragma unroll
        for (int j = 0; j < 4; j++) dst[j] = u.v[j];
        return;
    }

    // ---- xm finish (coalesced float writes) ----
    {
        int w    = blockIdx.x * 8 + (tid >> 5);   // 0..255
        int lane = tid & 31;
        int i4   = w & 31;
        int b    = (w >> 5) * 32 + lane;
        float4 a = g_xmp[0][b][i4];
#pragma unroll
        for (int q = 1; q < 4; q++) {
            float4 v = g_xmp[q][b][i4];
            a.x += v.x; a.y += v.y; a.z += v.z; a.w += v.w;
        }
        const float k = 1.0f / SS;
        g_xmf[(i4 * 4 + 0) * BSZ + b] = a.x * k;
        g_xmf[(i4 * 4 + 1) * BSZ + b] = a.y * k;
        g_xmf[(i4 * 4 + 2) * BSZ + b] = a.z * k;
        g_xmf[(i4 * 4 + 3) * BSZ + b] = a.w * k;
    }

    // ---- hist transpose ----
    __shared__ __align__(16) __half t[128][BT][12];   // 24576B
    int b0 = blockIdx.x * BT;
#pragma unroll
    for (int bb = 0; bb < BT; bb++) {
        int b = b0 + bb;
        for (int idx = tid; idx < 12 * 128; idx += 256) {
            int r = idx >> 7, i = idx & 127;
            __half v = __float2half(0.0f);
            int l = 11;
            if (r < 11) {          // row r holds s = SS-11+r  ->  lag l = 10-r
                l = 10 - r;
                v = __float2half(x[((size_t)b * SS + (SS - 11 + r)) * II + i]);
            }
            t[i][bb][l] = v;
        }
    }
    __syncthreads();

    const uint4* s4 = reinterpret_cast<const uint4*>(&t[0][0][0]);
    int boff = (b0 * 3) >> 1;
    for (int c = tid; c < 1536; c += 256) {
        int i = c / 12, j = c - i * 12;
        g_hist4[(size_t)i * 384 + boff + j] = s4[c];
    }
}

// ---------------------------------------------------------------------------
// One (b,o,i) from smem params + hist regs + xm.
// ---------------------------------------------------------------------------
__device__ __forceinline__ float eval(const uint4* __restrict__ sp, int ii,
                                      uint2 ha, uint2 hb, uint2 hc, float xm) {
    UP2 u;
#pragma unroll
    for (int j = 0; j < 4; j++) u.v[j] = sp[ii * 4 + j];

    __half2 d = __hmul2(*reinterpret_cast<__half2*>(&ha.x), u.p.wl2[0]);
    d = __hfma2(*reinterpret_cast<__half2*>(&ha.y), u.p.wl2[1], d);
    d = __hfma2(*reinterpret_cast<__half2*>(&hb.x), u.p.wl2[2], d);
    d = __hfma2(*reinterpret_cast<__half2*>(&hb.y), u.p.wl2[3], d);
    d = __hfma2(*reinterpret_cast<__half2*>(&hc.x), u.p.wl2[4], d);
    d = __hfma2(*reinterpret_cast<__half2*>(&hc.y), u.p.wl2[5], d);
    float2 df = __half22float2(d);
    float xl = df.x + df.y;

    float s   = sigmoid_t(xl);
    float idx = s * 4.0f;
    int   k   = (int)idx;
    k = (k > 3) ? 3 : k;
    float w1f = idx - (float)k;
    float c0 = (k == 0) ? u.p.C[0] : (k == 1) ? u.p.C[1] : (k == 2) ? u.p.C[2] : u.p.C[3];
    float c1 = (k == 0) ? u.p.C[1] : (k == 1) ? u.p.C[2] : (k == 2) ? u.p.C[3] : u.p.C[4];
    float y  = fmaf(c1 - c0, w1f, c0);

    float acc = fmaf(fmaf(fmaf(u.p.K3, xm, u.p.K2), xm, u.p.K1), xm, u.p.A0);
    float alpha = sigmoid_t(acc);
    return y * alpha;
}

// ---------------------------------------------------------------------------
// Kernel 3: main.  block = o-quad x i-chunk, 256 threads = 256 b.
// One hist/xm load feeds 4 independent eval chains (ILP x4); params staged
// to smem; hist/xm register-prefetched 1 ahead.  grid = (32, 12), occ 3.
// ---------------------------------------------------------------------------
__global__ __launch_bounds__(256, 3) void main_kernel(float* __restrict__ out)
{
    __shared__ __align__(16) uint4 spar[OQ][MAXL * 4];   // 2816B

    int b  = threadIdx.x;
    int o0 = blockIdx.x * OQ;
    int ch = blockIdx.y;
    int i0  = (ch < 8) ? ch * 11 : 88 + (ch - 8) * 10;
    int len = (ch < 8) ? 11 : 10;

    // stage all 4 o's params for this i-chunk
    {
        for (int oo = 0; oo < OQ; oo++) {
            const uint4* pg = g_pp2 + (size_t)((o0 + oo) * II + i0) * 4;
            uint32_t sb = (uint32_t)__cvta_generic_to_shared(&spar[oo][0]);
            for (int c = threadIdx.x; c < len * 4; c += 256)
                cp16(sb + c * 16, pg + c);
        }
        asm volatile("cp.async.commit_group;");
        asm volatile("cp.async.wait_group 0;");
    }
    __syncthreads();

    const uint2* hp = reinterpret_cast<const uint2*>(g_hist4) + ((size_t)i0 * BSZ + b) * 3;
    const float* xp = g_xmf + (size_t)i0 * BSZ + b;

    uint2 ha = hp[0], hb = hp[1], hc = hp[2];
    float xm = *xp;
    float acc0 = 0.0f, acc1 = 0.0f, acc2 = 0.0f, acc3 = 0.0f;

    for (int ii = 0; ii < len; ii++) {
        uint2 na = ha, nb = hb, nc = hc;
        float nx = xm;
        if (ii + 1 < len) {
            const uint2* q = hp + (size_t)(ii + 1) * BSZ * 3;
            na = q[0]; nb = q[1]; nc = q[2];
            nx = xp[(size_t)(ii + 1) * BSZ];
        }

        acc0 += eval(spar[0], ii, ha, hb, hc, xm);
        acc1 += eval(spar[1], ii, ha, hb, hc, xm);
        acc2 += eval(spar[2], ii, ha, hb, hc, xm);
        acc3 += eval(spar[3], ii, ha, hb, hc, xm);

        ha = na; hb = nb; hc = nc; xm = nx;
    }

    float* op = out + (size_t)b * OO + o0;
    atomicAdd(op,     acc0);
    atomicAdd(op + 1, acc1);
    atomicAdd(op + 2, acc2);
    atomicAdd(op + 3, acc3);
}

extern "C" void kernel_launch(void* const* d_in, const int* in_sizes, int n_in,
                              void* d_out, int out_size) {
    const float* x      = (const float*)d_in[0];
    const float* coeffs = (const float*)d_in[1];
    const float* lag    = (const float*)d_in[2];
    const float* mw1    = (const float*)d_in[3];
    const float* mb1    = (const float*)d_in[4];
    const float* mw2    = (const float*)d_in[5];
    const float* mb2    = (const float*)d_in[6];
    const float* edge   = (const float*)d_in[7];
    float* out = (float*)d_out;

    dim3 xg(BSZ, 4);
    xm_kernel<<<xg, 256>>>(x, out);
    prep_kernel<<<96, 256>>>(x, coeffs, lag, mw1, mb1, mw2, mb2, edge);
    dim3 grid(OO / OQ, ICH);
    main_kernel<<<grid, 256>>>(out);
}